// round 5
// baseline (speedup 1.0000x reference)
#include <cuda_runtime.h>
#include <cuda_bf16.h>
#include <cstdint>

// PowerSpectrum: out[n, l*512 + q*16 + p] = cg[l] * sum_m x_nu[l,n,m,q] * x_1[l,n,m,p]
// L=4, M=7, F_NU=32, F_1=16.
//
// Round-5: persistent warps + cp.async double-buffered pipeline.
// Each warp owns a fixed l and strides over n. Per iteration it issues the next
// tile's cp.async (global->shared, no register hop) into the alternate buffer,
// waits for the current tile (wait_group 1), computes, stores. DRAM latency is
// overlapped with the previous tile's compute. Compute/store mapping = R4:
// lane j owns p-quad (j&3)*4 and q=(j>>2)+8k; every STG.128 is contiguous 512B.

#define PS_L  4
#define PS_M  7
#define PS_FN 32
#define PS_FP 16
#define OUT_PER_N (PS_L * PS_FN * PS_FP)   // 2048
#define WARPS_PER_CTA 8                    // 2 n-chains x 4 l-channels
#define F4_PER_TILE 84                     // 56 (x_nu) + 28 (x_1) float4 per (n,l)

#define CP16(dst_u32, src_ptr)                                           \
    asm volatile("cp.async.cg.shared.global [%0], [%1], 16;" ::          \
                 "r"(dst_u32), "l"(src_ptr))
#define CP_COMMIT() asm volatile("cp.async.commit_group;")
#define CP_WAIT1()  asm volatile("cp.async.wait_group 1;")

__global__ __launch_bounds__(32 * WARPS_PER_CTA)
void ps_kernel(const float* __restrict__ x_nu,
               const float* __restrict__ x_1,
               float* __restrict__ out,
               int N)
{
    // per-warp double buffer: [warp][buf][84 float4]
    __shared__ float4 sm[WARPS_PER_CTA * 2 * F4_PER_TILE];

    const int t = threadIdx.x;
    const int w = t >> 5;                  // warp 0..7
    const int j = t & 31;                  // lane
    const int s = w >> 2;                  // chain slot within CTA (0..1)
    const int l = w & 3;                   // angular channel

    const int chain  = blockIdx.x * 2 + s; // n-chain id
    const int stride = gridDim.x * 2;

    const float4* gx_base = reinterpret_cast<const float4*>(x_nu) + (size_t)l * N * 56;
    const float4* g1_base = reinterpret_cast<const float4*>(x_1)  + (size_t)l * N * 28;

    const uint32_t smw0 = (uint32_t)__cvta_generic_to_shared(sm + (w * 2) * F4_PER_TILE);
    // issue cp.async group for sample n into buffer b (3 LDGSTS.128/lane, 2 predicated)
    auto issue = [&](int n, int b) {
        const uint32_t dst = smw0 + (uint32_t)b * (F4_PER_TILE * 16);
        const float4* gx = gx_base + (size_t)n * 56;
        const float4* g1 = g1_base + (size_t)n * 28;
        CP16(dst + j * 16, gx + j);
        if (j < 24) { CP16(dst + (32 + j) * 16, gx + 32 + j); }
        else        { CP16(dst + (32 + j) * 16, g1 + (j - 24)); }
        if (j < 20) { CP16(dst + (64 + j) * 16, g1 + 8 + j); }
    };

    const int qb = j >> 2;                 // q base 0..7 (q = qb + 8k)
    const int pq = j & 3;                  // p-quad (p = pq*4 .. pq*4+3)
    const float cgs[PS_L] = {1.0f, 0.57735026918962576f,
                             0.44721359549995794f, 0.37796447300922722f};
    const float cg = cgs[l];

    // prologue
    if (chain < N) issue(chain, 0);
    CP_COMMIT();

    int buf = 0;
    for (int n = chain; n < N; n += stride) {
        const int nn = n + stride;
        if (nn < N) issue(nn, buf ^ 1);
        CP_COMMIT();
        CP_WAIT1();                        // tile for n is resident
        __syncwarp();

        const float4* smw = sm + (w * 2 + buf) * F4_PER_TILE;
        const float*  an  = reinterpret_cast<const float*>(smw);   // x_nu: [m*32 + q]
        const float4* bp  = smw + 56 + pq;                         // x_1:  [m*4 + pq]

        float4 acc0 = make_float4(0.f, 0.f, 0.f, 0.f);
        float4 acc1 = acc0, acc2 = acc0, acc3 = acc0;

#pragma unroll
        for (int m = 0; m < PS_M; m++) {
            const float4 b = bp[m * 4];
            const float a0 = an[m * PS_FN + qb +  0];
            const float a1 = an[m * PS_FN + qb +  8];
            const float a2 = an[m * PS_FN + qb + 16];
            const float a3 = an[m * PS_FN + qb + 24];

            acc0.x = fmaf(a0, b.x, acc0.x);
            acc0.y = fmaf(a0, b.y, acc0.y);
            acc0.z = fmaf(a0, b.z, acc0.z);
            acc0.w = fmaf(a0, b.w, acc0.w);
            acc1.x = fmaf(a1, b.x, acc1.x);
            acc1.y = fmaf(a1, b.y, acc1.y);
            acc1.z = fmaf(a1, b.z, acc1.z);
            acc1.w = fmaf(a1, b.w, acc1.w);
            acc2.x = fmaf(a2, b.x, acc2.x);
            acc2.y = fmaf(a2, b.y, acc2.y);
            acc2.z = fmaf(a2, b.z, acc2.z);
            acc2.w = fmaf(a2, b.w, acc2.w);
            acc3.x = fmaf(a3, b.x, acc3.x);
            acc3.y = fmaf(a3, b.y, acc3.y);
            acc3.z = fmaf(a3, b.z, acc3.z);
            acc3.w = fmaf(a3, b.w, acc3.w);
        }

        acc0.x *= cg; acc0.y *= cg; acc0.z *= cg; acc0.w *= cg;
        acc1.x *= cg; acc1.y *= cg; acc1.z *= cg; acc1.w *= cg;
        acc2.x *= cg; acc2.y *= cg; acc2.z *= cg; acc2.w *= cg;
        acc3.x *= cg; acc3.y *= cg; acc3.z *= cg; acc3.w *= cg;

        float4* o = reinterpret_cast<float4*>(
            out + (size_t)n * OUT_PER_N + l * (PS_FN * PS_FP));
        o[j +  0] = acc0;
        o[j + 32] = acc1;
        o[j + 64] = acc2;
        o[j + 96] = acc3;

        buf ^= 1;
    }
}

extern "C" void kernel_launch(void* const* d_in, const int* in_sizes, int n_in,
                              void* d_out, int out_size)
{
    const float* x_nu = (const float*)d_in[0];
    const float* x_1  = (const float*)d_in[1];
    float* out = (float*)d_out;

    const int N = in_sizes[0] / (PS_L * PS_M * PS_FN);

    int grid = 148 * 8;                    // persistent: 8 CTAs per SM
    if (grid > (N + 1) / 2) grid = (N + 1) / 2;

    ps_kernel<<<grid, 32 * WARPS_PER_CTA>>>(x_nu, x_1, out, N);
}